// round 17
// baseline (speedup 1.0000x reference)
#include <cuda_runtime.h>
#include <cuda_bf16.h>

#define R_EARTH  6371000.0f
#define DEG2RADF 0.017453292519943295f
#define DT_SEC   600.0f
#define NSTEPS   48
#define NPAIRS   (NSTEPS / 2)

#define WOUT4 120         // output columns per warp (32 lanes * 4 - 2*4 halo)
#define SH    64          // output rows per strip
#define WPB   8           // warps per block

// Static device buffers — NOT allocations.
__device__ __align__(16) float g_scratch[8u * 1024u * 1024u];  // T ping-pong
__device__ __align__(16) float g_P[8u * 1024u * 1024u];        // -DT*mask*ug*inv2dx
__device__ __align__(16) float g_Q[8u * 1024u * 1024u];        // -DT*mask*vg*inv2dy

__device__ float g_inv_2dx[4096];
__device__ float g_inv_2dy;

__global__ void setup_kernel(const float* __restrict__ lat,
                             const float* __restrict__ lon, int H) {
    float dlat = lat[1] - lat[0];
    float dlon = lon[1] - lon[0];
    float dy = R_EARTH * DEG2RADF * dlat;
    if (blockIdx.x == 0 && threadIdx.x == 0)
        g_inv_2dy = 0.5f / dy;
    float dx0 = R_EARTH * DEG2RADF * dlon;
    for (int i = blockIdx.x * blockDim.x + threadIdx.x; i < H;
         i += gridDim.x * blockDim.x) {
        float dx = dx0 * cosf(lat[i] * DEG2RADF);
        g_inv_2dx[i] = 0.5f / dx;
    }
}

// P/Q are step-invariant: fold -DT * mask * metric into the velocity fields.
__global__ void precompute_pq(const float* __restrict__ ug,
                              const float* __restrict__ vg,
                              const float* __restrict__ mask, int H, int W) {
    int p = blockIdx.x * blockDim.x + threadIdx.x;   // plane index
    int b = blockIdx.y;
    if (p >= H * W) return;
    int row = p / W;
    int idx = b * H * W + p;
    float s = -DT_SEC * mask[p];
    g_P[idx] = s * ug[idx] * g_inv_2dx[row];
    g_Q[idx] = s * vg[idx] * g_inv_2dy;
}

// TWO fused timesteps per launch; register-rolling y-sweep, float4 per lane.
// Lane l carries columns x..x+3 with x = wc*120 + 4*l - 4 (1-lane halo/side).
// Stage 1: T1 = step(T) in rolling registers; stage 2 (two rows behind):
// T2 = step(T1), stored. x-neighbors: in-register + 2 shuffles per exchange.
// Grid is <= 148 blocks (one per SM), so registers are spent freely on a
// 4-row double-buffered prefetch to hide DRAM latency within each warp.
__global__ __launch_bounds__(256, 1)
void step2_kernel(const float* __restrict__ src_ext, int src_is_scratch,
                  float* __restrict__ dst_ext, int dst_is_scratch,
                  const float* __restrict__ mask, int H, int W,
                  int NXW, int NYS, int total_warps) {
    const float* __restrict__ src = src_is_scratch ? g_scratch : src_ext;
    float* __restrict__       dst = dst_is_scratch ? g_scratch : dst_ext;

    const int lane = threadIdx.x & 31;
    const int wu   = blockIdx.x * WPB + (threadIdx.x >> 5);
    if (wu >= total_warps) return;

    const int wc = wu % NXW;
    const int ys = (wu / NXW) % NYS;
    const int b  = wu / (NXW * NYS);

    const int x  = wc * WOUT4 + 4 * lane - 4;        // 4-aligned quad start
    int xp = x < 0 ? 0 : (x > W - 4 ? W - 4 : x);    // clamped, 4-aligned
    const bool in_x = (x >= 0) && (x <= W - 4);      // whole quad in domain
    const bool store_lane = in_x && (lane >= 1) && (lane <= 30);
    const bool x_lo = (x == 0);
    const bool x_hi = (x + 3 == W - 1);
    const float xf_lo = x_lo ? 2.0f : 1.0f;          // one-sided dx factors
    const float xf_hi = x_hi ? 2.0f : 1.0f;

    const int y0 = ys * SH;
    const int y1 = min(y0 + SH, H);

    const int plane = H * W;
    const float* __restrict__ Tb = src + b * plane + xp;
    const float* __restrict__ Pb = g_P + b * plane + xp;
    const float* __restrict__ Qb = g_Q + b * plane + xp;
    const float* __restrict__ mb = mask + xp;
    float* __restrict__ dstb = dst + b * plane + xp;

    // ---- Rolling pipeline state (float4 = column quad) ----
    float4 t_m1, t_0;                                  // T rows r-1, r
    float4 hs1_m2 = {0,0,0,0}, hs1_m1 = {0,0,0,0};     // hbinom(A1) r-2, r-1
    float4 T1a = {0,0,0,0}, T1b = {0,0,0,0};           // T1 rows r-3, r-2
    float4 hs2_m2 = {0,0,0,0}, hs2_m1 = {0,0,0,0};     // hbinom(A2) r-4, r-3
    float4 m1 = {0,0,0,0}, m2 = {0,0,0,0}, m3 = {0,0,0,0};
    float4 Pd1 = {0,0,0,0}, Pd2 = {0,0,0,0};
    float4 Qd1 = {0,0,0,0}, Qd2 = {0,0,0,0};

    const int r0 = y0 - 3;
    {
        int ya = r0 - 1; ya = ya < 0 ? 0 : ya;
        int yb = r0;     yb = yb < 0 ? 0 : yb;
        t_m1 = *(const float4*)(Tb + ya * W);
        t_0  = *(const float4*)(Tb + yb * W);
    }

    auto iterate = [&](int r, float4 t_p1, float4 Pn, float4 Qn, float4 mn,
                       bool do_store) {
        // ---- stage 1: advected field A1 at row r ----
        float4 a1 = {0, 0, 0, 0};
        if (r >= 0 && r < H) {                         // warp-uniform
            float tl = __shfl_up_sync(0xffffffffu, t_0.w, 1);
            float tr = __shfl_down_sync(0xffffffffu, t_0.x, 1);
            float xl0 = x_lo ? t_0.x : tl;
            float xr3 = x_hi ? t_0.w : tr;
            float Qs = (r == 0 || r == H - 1) ? 2.0f : 1.0f;
            float4 yl = (r == 0)     ? t_0 : t_m1;
            float4 yh = (r == H - 1) ? t_0 : t_p1;
            a1.x = fmaf(Pn.x, t_0.y - xl0,   fmaf(Qs * Qn.x, yh.x - yl.x, t_0.x));
            a1.y = fmaf(Pn.y, t_0.z - t_0.x, fmaf(Qs * Qn.y, yh.y - yl.y, t_0.y));
            a1.z = fmaf(Pn.z, t_0.w - t_0.y, fmaf(Qs * Qn.z, yh.z - yl.z, t_0.z));
            a1.w = fmaf(Pn.w, xr3 - t_0.z,   fmaf(Qs * Qn.w, yh.w - yl.w, t_0.w));
            if (!in_x) a1 = make_float4(0, 0, 0, 0);   // zero pad at x edges
        }
        float au = __shfl_up_sync(0xffffffffu, a1.w, 1);
        float ad = __shfl_down_sync(0xffffffffu, a1.x, 1);
        float4 hs1_0;
        hs1_0.x = au   + 2.0f * a1.x + a1.y;
        hs1_0.y = a1.x + 2.0f * a1.y + a1.z;
        hs1_0.z = a1.y + 2.0f * a1.z + a1.w;
        hs1_0.w = a1.z + 2.0f * a1.w + ad;

        // T1 at row r-1 (vertical binomial * mask)
        float4 T1c;
        T1c.x = (hs1_m2.x + 2.0f * hs1_m1.x + hs1_0.x) * 0.0625f * m1.x;
        T1c.y = (hs1_m2.y + 2.0f * hs1_m1.y + hs1_0.y) * 0.0625f * m1.y;
        T1c.z = (hs1_m2.z + 2.0f * hs1_m1.z + hs1_0.z) * 0.0625f * m1.z;
        T1c.w = (hs1_m2.w + 2.0f * hs1_m1.w + hs1_0.w) * 0.0625f * m1.w;

        // ---- stage 2: advected field A2 at row r2 = r-2 (on T1) ----
        float4 a2 = {0, 0, 0, 0};
        int r2 = r - 2;
        if (r2 >= 0 && r2 < H) {                       // warp-uniform
            float tl = __shfl_up_sync(0xffffffffu, T1b.w, 1);
            float tr = __shfl_down_sync(0xffffffffu, T1b.x, 1);
            float xl0 = x_lo ? T1b.x : tl;
            float xr3 = x_hi ? T1b.w : tr;
            float Qs = (r2 == 0 || r2 == H - 1) ? 2.0f : 1.0f;
            float4 yl = (r2 == 0)     ? T1b : T1a;
            float4 yh = (r2 == H - 1) ? T1b : T1c;
            a2.x = fmaf(Pd2.x, T1b.y - xl0,   fmaf(Qs * Qd2.x, yh.x - yl.x, T1b.x));
            a2.y = fmaf(Pd2.y, T1b.z - T1b.x, fmaf(Qs * Qd2.y, yh.y - yl.y, T1b.y));
            a2.z = fmaf(Pd2.z, T1b.w - T1b.y, fmaf(Qs * Qd2.z, yh.z - yl.z, T1b.z));
            a2.w = fmaf(Pd2.w, xr3 - T1b.z,   fmaf(Qs * Qd2.w, yh.w - yl.w, T1b.w));
            if (!in_x) a2 = make_float4(0, 0, 0, 0);
        }
        float bu = __shfl_up_sync(0xffffffffu, a2.w, 1);
        float bd = __shfl_down_sync(0xffffffffu, a2.x, 1);
        float4 hs2_0;
        hs2_0.x = bu   + 2.0f * a2.x + a2.y;
        hs2_0.y = a2.x + 2.0f * a2.y + a2.z;
        hs2_0.z = a2.y + 2.0f * a2.z + a2.w;
        hs2_0.w = a2.z + 2.0f * a2.w + bd;

        // ---- output row o = r-3 ----
        if (do_store && store_lane) {
            float4 v;
            v.x = (hs2_m2.x + 2.0f * hs2_m1.x + hs2_0.x) * 0.0625f * m3.x;
            v.y = (hs2_m2.y + 2.0f * hs2_m1.y + hs2_0.y) * 0.0625f * m3.y;
            v.z = (hs2_m2.z + 2.0f * hs2_m1.z + hs2_0.z) * 0.0625f * m3.z;
            v.w = (hs2_m2.w + 2.0f * hs2_m1.w + hs2_0.w) * 0.0625f * m3.w;
            *(float4*)(dstb + (r - 3) * W) = v;
        }

        // ---- shift rolling state ----
        t_m1 = t_0;   t_0 = t_p1;
        hs1_m2 = hs1_m1; hs1_m1 = hs1_0;
        T1a = T1b;    T1b = T1c;
        hs2_m2 = hs2_m1; hs2_m1 = hs2_0;
        m3 = m2; m2 = m1; m1 = mn;
        Pd2 = Pd1; Pd1 = Pn;
        Qd2 = Qd1; Qd1 = Qn;
    };

    // ---- warm-up: 6 iterations (r = y0-3 .. y0+2), batched, no store ----
    {
        float4 tw[6], pw[6], qw[6], mw[6];
        #pragma unroll
        for (int j = 0; j < 6; j++) {
            int r  = r0 + j;
            int rt = r + 1; rt = rt < 0 ? 0 : (rt >= H ? H - 1 : rt);
            int rc = r;     rc = rc < 0 ? 0 : (rc >= H ? H - 1 : rc);
            tw[j] = *(const float4*)(Tb + rt * W);
            pw[j] = *(const float4*)(Pb + rc * W);
            pw[j].x *= xf_lo;  pw[j].w *= xf_hi;
            qw[j] = *(const float4*)(Qb + rc * W);
            mw[j] = *(const float4*)(mb + rc * W);
        }
        #pragma unroll
        for (int j = 0; j < 6; j++)
            iterate(r0 + j, tw[j], pw[j], qw[j], mw[j], false);
    }

    // ---- main loop: 4-row chunks, double-buffered prefetch ----
    const int iters = y1 - y0;                         // SH; H % SH == 0 here

#define LOADC(kk, tA, pA, qA, mA)                                   \
    {                                                               \
        _Pragma("unroll")                                           \
        for (int j = 0; j < 4; j++) {                               \
            int r  = y0 + 3 + (kk) + j;                             \
            int rt = r + 1 >= H ? H - 1 : r + 1;                    \
            int rc = r     >= H ? H - 1 : r;                        \
            tA[j] = *(const float4*)(Tb + rt * W);                  \
            pA[j] = *(const float4*)(Pb + rc * W);                  \
            pA[j].x *= xf_lo;  pA[j].w *= xf_hi;                    \
            qA[j] = *(const float4*)(Qb + rc * W);                  \
            mA[j] = *(const float4*)(mb + rc * W);                  \
        }                                                           \
    }
#define COMP4(kk, tA, pA, qA, mA)                                   \
    {                                                               \
        _Pragma("unroll")                                           \
        for (int j = 0; j < 4; j++)                                 \
            iterate(y0 + 3 + (kk) + j, tA[j], pA[j], qA[j], mA[j],  \
                    true);                                          \
    }

    float4 t0a[4], p0a[4], q0a[4], m0a[4];
    float4 t1a[4], p1a[4], q1a[4], m1a[4];

    LOADC(0, t0a, p0a, q0a, m0a);
    for (int k = 0; k < iters; k += 8) {
        LOADC(k + 4, t1a, p1a, q1a, m1a);
        COMP4(k, t0a, p0a, q0a, m0a);
        if (k + 8 < iters) LOADC(k + 8, t0a, p0a, q0a, m0a);
        COMP4(k + 4, t1a, p1a, q1a, m1a);
    }
#undef LOADC
#undef COMP4
}

extern "C" void kernel_launch(void* const* d_in, const int* in_sizes, int n_in,
                              void* d_out, int out_size) {
    const float* T    = (const float*)d_in[0];
    const float* ug   = (const float*)d_in[1];
    const float* vg   = (const float*)d_in[2];
    const float* lat  = (const float*)d_in[3];
    const float* lon  = (const float*)d_in[4];
    const float* mask = (const float*)d_in[5];
    float* out = (float*)d_out;

    const int H = in_sizes[3];
    const int W = in_sizes[4];
    const int B = in_sizes[0] / (H * W);

    setup_kernel<<<(H + 255) / 256, 256>>>(lat, lon, H);
    {
        dim3 g((H * W + 255) / 256, B);
        precompute_pq<<<g, 256>>>(ug, vg, mask, H, W);
    }

    const int NXW = (W + WOUT4 - 1) / WOUT4;
    const int NYS = (H + SH - 1) / SH;
    const int total_warps = B * NYS * NXW;
    const int blocks = (total_warps + WPB - 1) / WPB;

    // 24 fused launches; ping-pong so the final one writes d_out.
    for (int p = 0; p < NPAIRS; p++) {
        int dst_is_out = ((NPAIRS - 1 - p) % 2) == 0;   // last pair -> out
        int src_is_scratch, dst_is_scratch;
        const float* src_ext;
        float* dst_ext;
        if (p == 0) { src_ext = T; src_is_scratch = 0; }
        else {
            int prev_dst_is_out = ((NPAIRS - p) % 2) == 0;
            if (prev_dst_is_out) { src_ext = out; src_is_scratch = 0; }
            else                 { src_ext = nullptr; src_is_scratch = 1; }
        }
        if (dst_is_out) { dst_ext = out; dst_is_scratch = 0; }
        else            { dst_ext = nullptr; dst_is_scratch = 1; }

        step2_kernel<<<blocks, 256>>>(src_ext, src_is_scratch,
                                      dst_ext, dst_is_scratch,
                                      mask, H, W,
                                      NXW, NYS, total_warps);
    }
}